// round 1
// baseline (speedup 1.0000x reference)
#include <cuda_runtime.h>
#include <math.h>
#include <stdint.h>

// Problem constants
#define B_  2
#define T_  4096
#define C_  768
#define H_  12
#define D_  64
#define NQKV_ (3 * C_)   // 2304
#define M_  (B_ * T_)    // 8192

// Scratch (allocation-free rule: __device__ globals)
__device__ float g_Q[B_ * H_ * T_ * D_];   // 24 MB
__device__ float g_K[B_ * H_ * T_ * D_];   // 24 MB
__device__ float g_V[B_ * H_ * T_ * D_];   // 24 MB
__device__ float g_Y[B_ * T_ * C_];        // 24 MB

// ---------------------------------------------------------------------------
// GEMM1: C[m,n] = sum_k x[m,k] * w_qkv[k,n], scattered into Q/K/V head-major
// 128x128 tile, BK=8, 256 threads, 8x8 per thread.
// ---------------------------------------------------------------------------
__global__ __launch_bounds__(256) void gemm_qkv_kernel(
    const float* __restrict__ A,   // [M_, C_]
    const float* __restrict__ W)   // [C_, NQKV_]
{
    __shared__ float As[8][132];   // padded: conflict-free transposed stores
    __shared__ float Bs[8][128];

    const int tid = threadIdx.x;
    const int bm = blockIdx.y * 128;
    const int bn = blockIdx.x * 128;

    const int arow = tid >> 1;            // 0..127
    const int acol = (tid & 1) * 4;       // 0 or 4
    const int brow = tid >> 5;            // 0..7
    const int bcol = (tid & 31) * 4;      // 0..124

    const int ty = tid >> 4;              // 0..15
    const int tx = tid & 15;              // 0..15

    const float* Aptr = A + (size_t)(bm + arow) * C_ + acol;
    const float* Bptr = W + (size_t)brow * NQKV_ + bn + bcol;

    float c[8][8];
#pragma unroll
    for (int i = 0; i < 8; i++)
#pragma unroll
        for (int j = 0; j < 8; j++) c[i][j] = 0.f;

    for (int k0 = 0; k0 < C_; k0 += 8) {
        float4 av = *(const float4*)(Aptr + k0);
        As[acol + 0][arow] = av.x;
        As[acol + 1][arow] = av.y;
        As[acol + 2][arow] = av.z;
        As[acol + 3][arow] = av.w;
        float4 bv = *(const float4*)(Bptr + (size_t)k0 * NQKV_);
        *(float4*)&Bs[brow][bcol] = bv;
        __syncthreads();
#pragma unroll
        for (int kk = 0; kk < 8; kk++) {
            float4 a0 = *(const float4*)&As[kk][ty * 8];
            float4 a1 = *(const float4*)&As[kk][ty * 8 + 4];
            float4 b0 = *(const float4*)&Bs[kk][tx * 8];
            float4 b1 = *(const float4*)&Bs[kk][tx * 8 + 4];
            float a[8] = {a0.x, a0.y, a0.z, a0.w, a1.x, a1.y, a1.z, a1.w};
            float b[8] = {b0.x, b0.y, b0.z, b0.w, b1.x, b1.y, b1.z, b1.w};
#pragma unroll
            for (int i = 0; i < 8; i++)
#pragma unroll
                for (int j = 0; j < 8; j++) c[i][j] = fmaf(a[i], b[j], c[i][j]);
        }
        __syncthreads();
    }

    // Scatter epilogue into Q/K/V [B,H,T,D]
#pragma unroll
    for (int i = 0; i < 8; i++) {
        const int m = bm + ty * 8 + i;
        const int b = m >> 12;          // / T_
        const int t = m & (T_ - 1);
#pragma unroll
        for (int j = 0; j < 8; j++) {
            const int n = bn + tx * 8 + j;
            const int sec = n / C_;             // 0=q,1=k,2=v
            const int r = n - sec * C_;
            const int h = r >> 6;
            const int d = r & 63;
            float* dst = (sec == 0) ? g_Q : (sec == 1) ? g_K : g_V;
            dst[((size_t)(b * H_ + h) * T_ + t) * D_ + d] = c[i][j];
        }
    }
}

// ---------------------------------------------------------------------------
// Flash attention: one CTA per (qtile, b*h). BQ=BK=64, 256 threads, 4x4 blk.
// ---------------------------------------------------------------------------
#define PAD 65
#define FA_SMEM_FLOATS (4 * 64 * PAD + 3 * 64)

__global__ __launch_bounds__(256) void flash_kernel()
{
    extern __shared__ float sm[];
    float* Qs  = sm;                    // [64][PAD]
    float* Ks  = Qs + 64 * PAD;
    float* Vs  = Ks + 64 * PAD;
    float* Ss  = Vs + 64 * PAD;
    float* m_s = Ss + 64 * PAD;         // [64]
    float* l_s = m_s + 64;
    float* sc_s = l_s + 64;

    const int qt = blockIdx.x;          // 0..63
    const int bh = blockIdx.y;          // 0..23
    const int tid = threadIdx.x;
    const int tx = tid & 15, ty = tid >> 4;
    const int qbase = ty * 4, kbase = tx * 4;

    const size_t head_off = (size_t)bh * T_ * D_;
    const float* Qp = g_Q + head_off + (size_t)qt * 64 * D_;
    const float* Kp = g_K + head_off;
    const float* Vp = g_V + head_off;

    // Load Q tile
    for (int i = tid; i < 64 * D_; i += 256)
        Qs[(i >> 6) * PAD + (i & 63)] = Qp[i];
    if (tid < 64) { m_s[tid] = -1e30f; l_s[tid] = 0.f; }

    float acc[4][4];
#pragma unroll
    for (int i = 0; i < 4; i++)
#pragma unroll
        for (int j = 0; j < 4; j++) acc[i][j] = 0.f;

    const int nkt = qt + 1;
    for (int kt = 0; kt < nkt; ++kt) {
        __syncthreads();   // prev PV done (Ks/Vs/Ss free); Qs ready on first iter
        // Load K, V tiles
        for (int i = tid; i < 64 * D_; i += 256) {
            const int r = i >> 6, cc = i & 63;
            Ks[r * PAD + cc] = Kp[(size_t)kt * 64 * D_ + i];
            Vs[r * PAD + cc] = Vp[(size_t)kt * 64 * D_ + i];
        }
        __syncthreads();

        // S = Q K^T (4x4 per thread)
        float s[4][4];
#pragma unroll
        for (int i = 0; i < 4; i++)
#pragma unroll
            for (int j = 0; j < 4; j++) s[i][j] = 0.f;
#pragma unroll 4
        for (int d = 0; d < D_; ++d) {
            float a[4], bb[4];
#pragma unroll
            for (int i = 0; i < 4; i++) a[i] = Qs[(qbase + i) * PAD + d];
#pragma unroll
            for (int j = 0; j < 4; j++) bb[j] = Ks[(kbase + j) * PAD + d];
#pragma unroll
            for (int i = 0; i < 4; i++)
#pragma unroll
                for (int j = 0; j < 4; j++) s[i][j] = fmaf(a[i], bb[j], s[i][j]);
        }
        const bool diag = (kt == qt);
#pragma unroll
        for (int i = 0; i < 4; i++) {
            const int q = qbase + i;
#pragma unroll
            for (int j = 0; j < 4; j++) {
                const int k = kbase + j;
                float v = s[i][j] * 0.125f;       // 1/sqrt(64)
                if (diag && (k > q)) v = -1e30f;  // causal mask (tiles aligned)
                Ss[q * PAD + k] = v;
            }
        }
        __syncthreads();

        // Online softmax: 4 threads per row (lanes sub=tid&3 of same warp)
        {
            const int row = tid >> 2;
            const int sub = tid & 3;
            const float m_old = m_s[row];
            float mx = -1e30f;
#pragma unroll
            for (int kk = sub * 16; kk < sub * 16 + 16; kk++)
                mx = fmaxf(mx, Ss[row * PAD + kk]);
            mx = fmaxf(mx, __shfl_xor_sync(0xffffffffu, mx, 1));
            mx = fmaxf(mx, __shfl_xor_sync(0xffffffffu, mx, 2));
            mx = fmaxf(mx, m_old);
            float sum = 0.f;
#pragma unroll
            for (int kk = sub * 16; kk < sub * 16 + 16; kk++) {
                float p = __expf(Ss[row * PAD + kk] - mx);
                Ss[row * PAD + kk] = p;
                sum += p;
            }
            sum += __shfl_xor_sync(0xffffffffu, sum, 1);
            sum += __shfl_xor_sync(0xffffffffu, sum, 2);
            if (sub == 0) {
                const float sc = __expf(m_old - mx);
                m_s[row] = mx;
                sc_s[row] = sc;
                l_s[row] = l_s[row] * sc + sum;
            }
        }
        __syncthreads();

        // O = O*sc + P V
#pragma unroll
        for (int i = 0; i < 4; i++) {
            const float sc = sc_s[qbase + i];
#pragma unroll
            for (int j = 0; j < 4; j++) acc[i][j] *= sc;
        }
#pragma unroll 4
        for (int k = 0; k < 64; ++k) {
            float p[4], vv[4];
#pragma unroll
            for (int i = 0; i < 4; i++) p[i] = Ss[(qbase + i) * PAD + k];
#pragma unroll
            for (int j = 0; j < 4; j++) vv[j] = Vs[k * PAD + kbase + j];
#pragma unroll
            for (int i = 0; i < 4; i++)
#pragma unroll
                for (int j = 0; j < 4; j++) acc[i][j] = fmaf(p[i], vv[j], acc[i][j]);
        }
    }

    // Epilogue: write to g_Y in [B, T, C] layout
    const int b = bh / H_;
    const int h = bh % H_;
#pragma unroll
    for (int i = 0; i < 4; i++) {
        const int q = qbase + i;
        const int t = qt * 64 + q;
        const float inv = 1.f / l_s[q];
#pragma unroll
        for (int j = 0; j < 4; j++) {
            g_Y[((size_t)(b * T_ + t)) * C_ + h * D_ + kbase + j] = acc[i][j] * inv;
        }
    }
}

// ---------------------------------------------------------------------------
// GEMM2: out = g_Y @ w_proj  (8192 x 768 x 768)
// ---------------------------------------------------------------------------
__global__ __launch_bounds__(256) void gemm_proj_kernel(
    const float* __restrict__ W,   // [C_, C_]
    float* __restrict__ out)       // [M_, C_]
{
    __shared__ float As[8][132];
    __shared__ float Bs[8][128];

    const int tid = threadIdx.x;
    const int bm = blockIdx.y * 128;
    const int bn = blockIdx.x * 128;

    const int arow = tid >> 1;
    const int acol = (tid & 1) * 4;
    const int brow = tid >> 5;
    const int bcol = (tid & 31) * 4;
    const int ty = tid >> 4;
    const int tx = tid & 15;

    const float* Aptr = g_Y + (size_t)(bm + arow) * C_ + acol;
    const float* Bptr = W + (size_t)brow * C_ + bn + bcol;

    float c[8][8];
#pragma unroll
    for (int i = 0; i < 8; i++)
#pragma unroll
        for (int j = 0; j < 8; j++) c[i][j] = 0.f;

    for (int k0 = 0; k0 < C_; k0 += 8) {
        float4 av = *(const float4*)(Aptr + k0);
        As[acol + 0][arow] = av.x;
        As[acol + 1][arow] = av.y;
        As[acol + 2][arow] = av.z;
        As[acol + 3][arow] = av.w;
        float4 bv = *(const float4*)(Bptr + (size_t)k0 * C_);
        *(float4*)&Bs[brow][bcol] = bv;
        __syncthreads();
#pragma unroll
        for (int kk = 0; kk < 8; kk++) {
            float4 a0 = *(const float4*)&As[kk][ty * 8];
            float4 a1 = *(const float4*)&As[kk][ty * 8 + 4];
            float4 b0 = *(const float4*)&Bs[kk][tx * 8];
            float4 b1 = *(const float4*)&Bs[kk][tx * 8 + 4];
            float a[8] = {a0.x, a0.y, a0.z, a0.w, a1.x, a1.y, a1.z, a1.w};
            float b[8] = {b0.x, b0.y, b0.z, b0.w, b1.x, b1.y, b1.z, b1.w};
#pragma unroll
            for (int i = 0; i < 8; i++)
#pragma unroll
                for (int j = 0; j < 8; j++) c[i][j] = fmaf(a[i], b[j], c[i][j]);
        }
        __syncthreads();
    }

#pragma unroll
    for (int i = 0; i < 8; i++) {
        const int m = bm + ty * 8 + i;
#pragma unroll
        for (int j = 0; j < 8; j++) {
            const int n = bn + tx * 8 + j;
            out[(size_t)m * C_ + n] = c[i][j];
        }
    }
}

// ---------------------------------------------------------------------------
extern "C" void kernel_launch(void* const* d_in, const int* in_sizes, int n_in,
                              void* d_out, int out_size)
{
    const float* x      = (const float*)d_in[0];   // [B,T,C]
    const float* w_qkv  = (const float*)d_in[1];   // [C, 3C]
    const float* w_proj = (const float*)d_in[2];   // [C, C]
    float* out = (float*)d_out;

    // GEMM1: x @ w_qkv -> Q/K/V scratch
    gemm_qkv_kernel<<<dim3(NQKV_ / 128, M_ / 128), 256>>>(x, w_qkv);

    // Flash attention
    const int fa_smem = FA_SMEM_FLOATS * (int)sizeof(float);   // ~67.3 KB
    cudaFuncSetAttribute(flash_kernel,
                         cudaFuncAttributeMaxDynamicSharedMemorySize, fa_smem);
    flash_kernel<<<dim3(T_ / 64, B_ * H_), 256, fa_smem>>>();

    // GEMM2: Y @ w_proj -> out
    gemm_proj_kernel<<<dim3(C_ / 128, M_ / 128), 256>>>(w_proj, out);
}

// round 2
// speedup vs baseline: 3.7730x; 3.7730x over previous
#include <cuda_runtime.h>
#include <cuda_bf16.h>
#include <math.h>
#include <stdint.h>

#define B_  2
#define T_  4096
#define C_  768
#define H_  12
#define D_  64
#define NQKV_ 2304
#define M_  8192
#define BH_ (B_*H_)

typedef __nv_bfloat16 bf16;

// ---------------- device scratch (allocation-free rule) -------------------
__device__ __align__(16) bf16 g_xh[M_*C_],      g_xl[M_*C_];
__device__ __align__(16) bf16 g_wqkvT_h[NQKV_*C_], g_wqkvT_l[NQKV_*C_];
__device__ __align__(16) bf16 g_wpT_h[C_*C_],   g_wpT_l[C_*C_];
__device__ __align__(16) bf16 g_Qh[BH_*T_*D_],  g_Ql[BH_*T_*D_];
__device__ __align__(16) bf16 g_Kh[BH_*T_*D_],  g_Kl[BH_*T_*D_];
__device__ __align__(16) bf16 g_Vh[BH_*D_*T_],  g_Vl[BH_*D_*T_];   // [bh][d][t] (transposed!)
__device__ __align__(16) bf16 g_Yh[M_*C_],      g_Yl[M_*C_];

// ---------------- helpers -------------------------------------------------
__device__ __forceinline__ void mma16816(float c[4], const uint32_t a[4], const uint32_t b[2]) {
    asm volatile("mma.sync.aligned.m16n8k16.row.col.f32.bf16.bf16.f32 "
        "{%0,%1,%2,%3}, {%4,%5,%6,%7}, {%8,%9}, {%0,%1,%2,%3};\n"
        : "+f"(c[0]), "+f"(c[1]), "+f"(c[2]), "+f"(c[3])
        : "r"(a[0]), "r"(a[1]), "r"(a[2]), "r"(a[3]), "r"(b[0]), "r"(b[1]));
}

__device__ __forceinline__ void cp16(void* dst, const void* src) {
    unsigned d = (unsigned)__cvta_generic_to_shared(dst);
    asm volatile("cp.async.cg.shared.global [%0], [%1], 16;\n" :: "r"(d), "l"(src));
}
__device__ __forceinline__ void cp_commit() { asm volatile("cp.async.commit_group;\n"); }
template<int N> __device__ __forceinline__ void cp_wait() {
    asm volatile("cp.async.wait_group %0;\n" :: "n"(N));
}

__device__ __forceinline__ void split2(float v, bf16& h, bf16& l) {
    h = __float2bfloat16(v);
    l = __float2bfloat16(v - __bfloat162float(h));
}

// exp2 on the FMA pipe (MUFU on B300 is only 0.5/cyc/SM)
__device__ __forceinline__ float fast_exp2(float y) {
    y = fmaxf(y, -120.f);
    float t = y + 12582912.f;              // round-to-nearest-int magic
    int   yi = __float_as_int(t) - 0x4B400000;
    float f  = y - (t - 12582912.f);
    float p = 1.3333558146e-3f;
    p = fmaf(p, f, 9.6181291076e-3f);
    p = fmaf(p, f, 5.5504108664e-2f);
    p = fmaf(p, f, 2.4022650696e-1f);
    p = fmaf(p, f, 6.9314718056e-1f);
    p = fmaf(p, f, 1.0f);
    return p * __int_as_float((yi + 127) << 23);
}

__device__ __forceinline__ void pack_split(float a, float b, uint32_t& ph, uint32_t& pl) {
    bf16 ah, al, bh, bl;
    split2(a, ah, al); split2(b, bh, bl);
    __nv_bfloat162 Hh; Hh.x = ah; Hh.y = bh;
    __nv_bfloat162 Ll; Ll.x = al; Ll.y = bl;
    ph = *(uint32_t*)&Hh; pl = *(uint32_t*)&Ll;
}

// ---------------- prep kernels -------------------------------------------
__global__ __launch_bounds__(256) void split_x_kernel(const float* __restrict__ x) {
    size_t i = ((size_t)blockIdx.x * 256 + threadIdx.x) * 4;
    float4 v = *(const float4*)(x + i);
    bf16 h0,l0,h1,l1,h2,l2,h3,l3;
    split2(v.x,h0,l0); split2(v.y,h1,l1); split2(v.z,h2,l2); split2(v.w,h3,l3);
    __nv_bfloat162 a,b,c,d;
    a.x=h0; a.y=h1; b.x=h2; b.y=h3; c.x=l0; c.y=l1; d.x=l2; d.y=l3;
    *(__nv_bfloat162*)(g_xh + i)     = a;
    *(__nv_bfloat162*)(g_xh + i + 2) = b;
    *(__nv_bfloat162*)(g_xl + i)     = c;
    *(__nv_bfloat162*)(g_xl + i + 2) = d;
}

// transpose + split: in f32 [K][N] -> out bf16 [N][K] hi/lo. mode 0: wqkv, 1: wproj
__global__ __launch_bounds__(256) void tsplit_kernel(const float* __restrict__ w,
                                                     int K, int N, int mode) {
    __shared__ float tile[32][33];
    bf16* outh = mode == 0 ? g_wqkvT_h : g_wpT_h;
    bf16* outl = mode == 0 ? g_wqkvT_l : g_wpT_l;
    const int n0 = blockIdx.x * 32, k0 = blockIdx.y * 32;
    const int tx = threadIdx.x & 31, ty = threadIdx.x >> 5;   // 32x8
#pragma unroll
    for (int r = 0; r < 32; r += 8)
        tile[ty + r][tx] = w[(size_t)(k0 + ty + r) * N + n0 + tx];
    __syncthreads();
#pragma unroll
    for (int r = 0; r < 32; r += 8) {
        float v = tile[tx][ty + r];
        bf16 h, l; split2(v, h, l);
        size_t o = (size_t)(n0 + ty + r) * K + k0 + tx;
        outh[o] = h; outl[o] = l;
    }
}

// ---------------- GEMM (MODE 1: x@wqkv->QKV scatter, MODE 2: Y@wproj->out)
__device__ __forceinline__ void epi_qkv(int m, int n, float v0, float v1) {
    const int b = m >> 12, t = m & 4095;
    const int sec = n / C_, r = n - sec * C_;
    const int h = r >> 6, d = r & 63;
    const int bh = b * H_ + h;
    bf16 h0, l0, h1, l1;
    split2(v0, h0, l0); split2(v1, h1, l1);
    if (sec == 2) {                        // V transposed: [bh][d][t]
        size_t o = ((size_t)bh * D_ + d) * T_ + t;
        g_Vh[o] = h0; g_Vl[o] = l0;
        g_Vh[o + T_] = h1; g_Vl[o + T_] = l1;
    } else {
        size_t o = ((size_t)bh * T_ + t) * D_ + d;
        bf16* dh = sec == 0 ? g_Qh : g_Kh;
        bf16* dl = sec == 0 ? g_Ql : g_Kl;
        __nv_bfloat162 Hh; Hh.x = h0; Hh.y = h1;
        __nv_bfloat162 Ll; Ll.x = l0; Ll.y = l1;
        *(__nv_bfloat162*)(dh + o) = Hh;
        *(__nv_bfloat162*)(dl + o) = Ll;
    }
}

template<int MODE>
__global__ __launch_bounds__(256) void gemm_kernel(float* __restrict__ out) {
    extern __shared__ bf16 sm[];
    bf16* sAh = sm;
    bf16* sAl = sm + 2 * 5120;
    bf16* sBh = sm + 4 * 5120;
    bf16* sBl = sm + 6 * 5120;

    const bf16* Agh = (MODE == 1) ? g_xh : g_Yh;
    const bf16* Agl = (MODE == 1) ? g_xl : g_Yl;
    const bf16* Bgh = (MODE == 1) ? g_wqkvT_h : g_wpT_h;
    const bf16* Bgl = (MODE == 1) ? g_wqkvT_l : g_wpT_l;

    const int tid = threadIdx.x, wid = tid >> 5, lane = tid & 31;
    const int wm = wid >> 1, wn = wid & 1;
    const int lq = lane >> 2, cq = (lane & 3) << 1;
    const int bm = blockIdx.y * 128, bn = blockIdx.x * 128;

    float acc[2][8][4];
#pragma unroll
    for (int i = 0; i < 2; i++)
#pragma unroll
        for (int j = 0; j < 8; j++)
#pragma unroll
            for (int k = 0; k < 4; k++) acc[i][j][k] = 0.f;

#define LOAD_TILES(BUF, K0)                                                   \
    {                                                                         \
        _Pragma("unroll")                                                     \
        for (int i_ = 0; i_ < 2; i_++) {                                      \
            int c_ = tid + 256 * i_;                                          \
            int row_ = c_ >> 2;                                               \
            int ko_ = (c_ & 3) << 3;                                          \
            size_t ga_ = (size_t)(bm + row_) * C_ + (K0) + ko_;               \
            size_t gb_ = (size_t)(bn + row_) * C_ + (K0) + ko_;               \
            int so_ = (BUF) * 5120 + row_ * 40 + ko_;                         \
            cp16(sAh + so_, Agh + ga_);                                       \
            cp16(sAl + so_, Agl + ga_);                                       \
            cp16(sBh + so_, Bgh + gb_);                                       \
            cp16(sBl + so_, Bgl + gb_);                                       \
        }                                                                     \
    }

    LOAD_TILES(0, 0); cp_commit();
    int buf = 0;
    for (int kt = 0; kt < 24; kt++) {
        if (kt < 23) { LOAD_TILES(buf ^ 1, (kt + 1) * 32); cp_commit(); cp_wait<1>(); }
        else cp_wait<0>();
        __syncthreads();
#pragma unroll
        for (int kc = 0; kc < 2; kc++) {
            const int ko = kc * 16 + cq;
            uint32_t ah[2][4], al[2][4];
#pragma unroll
            for (int mc = 0; mc < 2; mc++) {
                const bf16* p = sAh + buf * 5120 + (wm * 32 + mc * 16 + lq) * 40 + ko;
                ah[mc][0] = *(const uint32_t*)p;
                ah[mc][1] = *(const uint32_t*)(p + 8 * 40);
                ah[mc][2] = *(const uint32_t*)(p + 8);
                ah[mc][3] = *(const uint32_t*)(p + 8 * 40 + 8);
                const bf16* q = sAl + buf * 5120 + (wm * 32 + mc * 16 + lq) * 40 + ko;
                al[mc][0] = *(const uint32_t*)q;
                al[mc][1] = *(const uint32_t*)(q + 8 * 40);
                al[mc][2] = *(const uint32_t*)(q + 8);
                al[mc][3] = *(const uint32_t*)(q + 8 * 40 + 8);
            }
#pragma unroll
            for (int nc = 0; nc < 8; nc++) {
                const bf16* p = sBh + buf * 5120 + (wn * 64 + nc * 8 + lq) * 40 + ko;
                uint32_t bh2[2] = { *(const uint32_t*)p, *(const uint32_t*)(p + 8) };
                const bf16* q = sBl + buf * 5120 + (wn * 64 + nc * 8 + lq) * 40 + ko;
                uint32_t bl2[2] = { *(const uint32_t*)q, *(const uint32_t*)(q + 8) };
#pragma unroll
                for (int mc = 0; mc < 2; mc++) {
                    mma16816(acc[mc][nc], ah[mc], bh2);
                    mma16816(acc[mc][nc], ah[mc], bl2);
                    mma16816(acc[mc][nc], al[mc], bh2);
                }
            }
        }
        __syncthreads();
        buf ^= 1;
    }

#pragma unroll
    for (int mc = 0; mc < 2; mc++)
#pragma unroll
        for (int nc = 0; nc < 8; nc++) {
            const int m = bm + wm * 32 + mc * 16 + lq;
            const int n = bn + wn * 64 + nc * 8 + cq;
            float* a = acc[mc][nc];
            if (MODE == 2) {
                *(float2*)&out[(size_t)m * C_ + n]       = make_float2(a[0], a[1]);
                *(float2*)&out[(size_t)(m + 8) * C_ + n] = make_float2(a[2], a[3]);
            } else {
                epi_qkv(m, n, a[0], a[1]);
                epi_qkv(m + 8, n, a[2], a[3]);
            }
        }
}

// ---------------- flash attention -----------------------------------------
#define SA_ 0.1803368801111204f     /* 0.125 * log2(e) */
#define FLASH_SMEM (4 * 64 * 72 * 2)

__global__ __launch_bounds__(256) void flash_kernel() {
    extern __shared__ bf16 fsm[];
    bf16* sKh = fsm;
    bf16* sKl = fsm + 64 * 72;
    bf16* sVh = fsm + 2 * 64 * 72;   // [d][key]
    bf16* sVl = fsm + 3 * 64 * 72;

    const int qt = (int)(gridDim.x - 1) - (int)blockIdx.x;   // heavy tiles first
    const int bh = blockIdx.y;
    const int tid = threadIdx.x, wid = tid >> 5, lane = tid & 31;
    const int lq = lane >> 2, cq = (lane & 3) << 1;
    const int row0 = qt * 128 + wid * 16 + lq;               // global q row (first)

    // Q fragments, register resident for the whole KV loop
    const size_t qoff = ((size_t)bh * T_ + row0) * D_;
    uint32_t qh[4][4], ql[4][4];
#pragma unroll
    for (int kc = 0; kc < 4; kc++) {
        const int c = kc * 16 + cq;
        qh[kc][0] = *(const uint32_t*)(g_Qh + qoff + c);
        qh[kc][1] = *(const uint32_t*)(g_Qh + qoff + 8 * D_ + c);
        qh[kc][2] = *(const uint32_t*)(g_Qh + qoff + c + 8);
        qh[kc][3] = *(const uint32_t*)(g_Qh + qoff + 8 * D_ + c + 8);
        ql[kc][0] = *(const uint32_t*)(g_Ql + qoff + c);
        ql[kc][1] = *(const uint32_t*)(g_Ql + qoff + 8 * D_ + c);
        ql[kc][2] = *(const uint32_t*)(g_Ql + qoff + c + 8);
        ql[kc][3] = *(const uint32_t*)(g_Ql + qoff + 8 * D_ + c + 8);
    }

    float oacc[8][4];
#pragma unroll
    for (int i = 0; i < 8; i++)
#pragma unroll
        for (int j = 0; j < 4; j++) oacc[i][j] = 0.f;
    float m0 = -1e30f, m1 = -1e30f, l0 = 0.f, l1 = 0.f;

    const bf16* Kb_h = g_Kh + (size_t)bh * T_ * D_;
    const bf16* Kb_l = g_Kl + (size_t)bh * T_ * D_;
    const bf16* Vb_h = g_Vh + (size_t)bh * D_ * T_;
    const bf16* Vb_l = g_Vl + (size_t)bh * D_ * T_;

    const int nkt = 2 * qt + 2;
    for (int kt = 0; kt < nkt; kt++) {
        __syncthreads();
        {   // K tile: [key][d];  V tile: [d][key] (already transposed globally)
            const bf16* ph = Kb_h + kt * 64 * D_;
            const bf16* pl = Kb_l + kt * 64 * D_;
#pragma unroll
            for (int c = tid; c < 512; c += 256) {
                const int r = c >> 3, off = (c & 7) << 3;
                *(float4*)(sKh + r * 72 + off) = *(const float4*)(ph + r * D_ + off);
                *(float4*)(sKl + r * 72 + off) = *(const float4*)(pl + r * D_ + off);
            }
#pragma unroll
            for (int c = tid; c < 512; c += 256) {
                const int r = c >> 3, off = (c & 7) << 3;   // r = d row, off over keys
                *(float4*)(sVh + r * 72 + off) = *(const float4*)(Vb_h + (size_t)r * T_ + kt * 64 + off);
                *(float4*)(sVl + r * 72 + off) = *(const float4*)(Vb_l + (size_t)r * T_ + kt * 64 + off);
            }
        }
        __syncthreads();

        // S = Q K^T
        float sacc[8][4];
#pragma unroll
        for (int i = 0; i < 8; i++)
#pragma unroll
            for (int j = 0; j < 4; j++) sacc[i][j] = 0.f;
#pragma unroll
        for (int kc = 0; kc < 4; kc++) {
            const int ko = kc * 16 + cq;
#pragma unroll
            for (int nc = 0; nc < 8; nc++) {
                const bf16* p = sKh + (nc * 8 + lq) * 72 + ko;
                uint32_t bh2[2] = { *(const uint32_t*)p, *(const uint32_t*)(p + 8) };
                const bf16* q = sKl + (nc * 8 + lq) * 72 + ko;
                uint32_t bl2[2] = { *(const uint32_t*)q, *(const uint32_t*)(q + 8) };
                mma16816(sacc[nc], qh[kc], bh2);
                mma16816(sacc[nc], qh[kc], bl2);
                mma16816(sacc[nc], ql[kc], bh2);
            }
        }

        // causal mask (only the two diagonal-straddling tiles need it)
        if (kt >= 2 * qt) {
            const int colb = kt * 64;
#pragma unroll
            for (int nc = 0; nc < 8; nc++) {
                const int c0 = colb + nc * 8 + cq;
                if (c0     > row0)     sacc[nc][0] = -1e30f;
                if (c0 + 1 > row0)     sacc[nc][1] = -1e30f;
                if (c0     > row0 + 8) sacc[nc][2] = -1e30f;
                if (c0 + 1 > row0 + 8) sacc[nc][3] = -1e30f;
            }
        }

        // online softmax (raw logits; 1/8 scale folded into exp2 factor)
        float mx0 = -1e30f, mx1 = -1e30f;
#pragma unroll
        for (int nc = 0; nc < 8; nc++) {
            mx0 = fmaxf(mx0, fmaxf(sacc[nc][0], sacc[nc][1]));
            mx1 = fmaxf(mx1, fmaxf(sacc[nc][2], sacc[nc][3]));
        }
        mx0 = fmaxf(mx0, __shfl_xor_sync(0xffffffffu, mx0, 1));
        mx0 = fmaxf(mx0, __shfl_xor_sync(0xffffffffu, mx0, 2));
        mx1 = fmaxf(mx1, __shfl_xor_sync(0xffffffffu, mx1, 1));
        mx1 = fmaxf(mx1, __shfl_xor_sync(0xffffffffu, mx1, 2));
        const float mn0 = fmaxf(m0, mx0), mn1 = fmaxf(m1, mx1);
        const float sc0 = fast_exp2((m0 - mn0) * SA_);
        const float sc1 = fast_exp2((m1 - mn1) * SA_);
        m0 = mn0; m1 = mn1;
        l0 *= sc0; l1 *= sc1;
#pragma unroll
        for (int dc = 0; dc < 8; dc++) {
            oacc[dc][0] *= sc0; oacc[dc][1] *= sc0;
            oacc[dc][2] *= sc1; oacc[dc][3] *= sc1;
        }

        // P = exp(S - m), packed straight into A-fragments (hi/lo split)
        uint32_t pah[4][4], pal[4][4];
#pragma unroll
        for (int kc = 0; kc < 4; kc++) {
            const float e0 = fast_exp2((sacc[2*kc][0]   - m0) * SA_);
            const float e1 = fast_exp2((sacc[2*kc][1]   - m0) * SA_);
            const float e2 = fast_exp2((sacc[2*kc][2]   - m1) * SA_);
            const float e3 = fast_exp2((sacc[2*kc][3]   - m1) * SA_);
            const float f0 = fast_exp2((sacc[2*kc+1][0] - m0) * SA_);
            const float f1 = fast_exp2((sacc[2*kc+1][1] - m0) * SA_);
            const float f2 = fast_exp2((sacc[2*kc+1][2] - m1) * SA_);
            const float f3 = fast_exp2((sacc[2*kc+1][3] - m1) * SA_);
            l0 += e0 + e1 + f0 + f1;
            l1 += e2 + e3 + f2 + f3;
            pack_split(e0, e1, pah[kc][0], pal[kc][0]);
            pack_split(e2, e3, pah[kc][1], pal[kc][1]);
            pack_split(f0, f1, pah[kc][2], pal[kc][2]);
            pack_split(f2, f3, pah[kc][3], pal[kc][3]);
        }

        // O += P V
#pragma unroll
        for (int kc = 0; kc < 4; kc++) {
            const int ko = kc * 16 + cq;
#pragma unroll
            for (int dc = 0; dc < 8; dc++) {
                const bf16* p = sVh + (dc * 8 + lq) * 72 + ko;
                uint32_t vh2[2] = { *(const uint32_t*)p, *(const uint32_t*)(p + 8) };
                const bf16* q = sVl + (dc * 8 + lq) * 72 + ko;
                uint32_t vl2[2] = { *(const uint32_t*)q, *(const uint32_t*)(q + 8) };
                mma16816(oacc[dc], pah[kc], vh2);
                mma16816(oacc[dc], pah[kc], vl2);
                mma16816(oacc[dc], pal[kc], vh2);
            }
        }
    }

    // finalize: quad-reduce l, normalize, write Y split-bf16 in [B,T,C]
    l0 += __shfl_xor_sync(0xffffffffu, l0, 1);
    l0 += __shfl_xor_sync(0xffffffffu, l0, 2);
    l1 += __shfl_xor_sync(0xffffffffu, l1, 1);
    l1 += __shfl_xor_sync(0xffffffffu, l1, 2);
    const float inv0 = 1.f / l0, inv1 = 1.f / l1;

    const int b = bh / H_, h = bh - b * H_;
    const size_t y0 = ((size_t)b * T_ + row0) * C_ + h * D_;
    const size_t y1 = ((size_t)b * T_ + row0 + 8) * C_ + h * D_;
#pragma unroll
    for (int dc = 0; dc < 8; dc++) {
        const int col = dc * 8 + cq;
        uint32_t ph, pl;
        pack_split(oacc[dc][0] * inv0, oacc[dc][1] * inv0, ph, pl);
        *(uint32_t*)(g_Yh + y0 + col) = ph;
        *(uint32_t*)(g_Yl + y0 + col) = pl;
        pack_split(oacc[dc][2] * inv1, oacc[dc][3] * inv1, ph, pl);
        *(uint32_t*)(g_Yh + y1 + col) = ph;
        *(uint32_t*)(g_Yl + y1 + col) = pl;
    }
}

// ---------------------------------------------------------------------------
extern "C" void kernel_launch(void* const* d_in, const int* in_sizes, int n_in,
                              void* d_out, int out_size)
{
    const float* x      = (const float*)d_in[0];
    const float* w_qkv  = (const float*)d_in[1];
    const float* w_proj = (const float*)d_in[2];
    float* out = (float*)d_out;

    // prep: split inputs to bf16 hi/lo (weights also transposed)
    split_x_kernel<<<(M_ * C_) / (256 * 4), 256>>>(x);
    tsplit_kernel<<<dim3(NQKV_ / 32, C_ / 32), 256>>>(w_qkv, C_, NQKV_, 0);
    tsplit_kernel<<<dim3(C_ / 32, C_ / 32), 256>>>(w_proj, C_, C_, 1);

    const int gsmem = 8 * 5120 * (int)sizeof(bf16);   // 80 KB
    cudaFuncSetAttribute(gemm_kernel<1>, cudaFuncAttributeMaxDynamicSharedMemorySize, gsmem);
    cudaFuncSetAttribute(gemm_kernel<2>, cudaFuncAttributeMaxDynamicSharedMemorySize, gsmem);
    const int fsmem = FLASH_SMEM;                      // 72 KB
    cudaFuncSetAttribute(flash_kernel, cudaFuncAttributeMaxDynamicSharedMemorySize, fsmem);

    gemm_kernel<1><<<dim3(NQKV_ / 128, M_ / 128), 256, gsmem>>>(nullptr);
    flash_kernel<<<dim3(T_ / 128, BH_), 256, fsmem>>>();
    gemm_kernel<2><<<dim3(C_ / 128, M_ / 128), 256, gsmem>>>(out);
}

// round 3
// speedup vs baseline: 4.9450x; 1.3106x over previous
#include <cuda_runtime.h>
#include <cuda_bf16.h>
#include <cuda_fp16.h>
#include <math.h>
#include <stdint.h>

#define B_  2
#define T_  4096
#define C_  768
#define H_  12
#define D_  64
#define NQKV_ 2304
#define M_  8192
#define BH_ (B_*H_)

typedef __nv_bfloat16 bf16;

// ---------------- device scratch (allocation-free rule) -------------------
__device__ __align__(16) bf16 g_xh[M_*C_],      g_xl[M_*C_];
__device__ __align__(16) bf16 g_wqkvT_h[NQKV_*C_], g_wqkvT_l[NQKV_*C_];
__device__ __align__(16) bf16 g_wpT_h[C_*C_],   g_wpT_l[C_*C_];
__device__ __align__(16) bf16 g_Qh[BH_*T_*D_],  g_Ql[BH_*T_*D_];
__device__ __align__(16) bf16 g_Kh[BH_*T_*D_],  g_Kl[BH_*T_*D_];
__device__ __align__(16) __half g_Vt[BH_*D_*T_];          // [bh][d][t], single fp16
__device__ __align__(16) bf16 g_Yh[M_*C_],      g_Yl[M_*C_];

// ---------------- helpers -------------------------------------------------
__device__ __forceinline__ void mma16816(float c[4], const uint32_t a[4], const uint32_t b[2]) {
    asm volatile("mma.sync.aligned.m16n8k16.row.col.f32.bf16.bf16.f32 "
        "{%0,%1,%2,%3}, {%4,%5,%6,%7}, {%8,%9}, {%0,%1,%2,%3};\n"
        : "+f"(c[0]), "+f"(c[1]), "+f"(c[2]), "+f"(c[3])
        : "r"(a[0]), "r"(a[1]), "r"(a[2]), "r"(a[3]), "r"(b[0]), "r"(b[1]));
}
__device__ __forceinline__ void mma16816h(float c[4], const uint32_t a[4], const uint32_t b[2]) {
    asm volatile("mma.sync.aligned.m16n8k16.row.col.f32.f16.f16.f32 "
        "{%0,%1,%2,%3}, {%4,%5,%6,%7}, {%8,%9}, {%0,%1,%2,%3};\n"
        : "+f"(c[0]), "+f"(c[1]), "+f"(c[2]), "+f"(c[3])
        : "r"(a[0]), "r"(a[1]), "r"(a[2]), "r"(a[3]), "r"(b[0]), "r"(b[1]));
}

__device__ __forceinline__ void cp16(void* dst, const void* src) {
    unsigned d = (unsigned)__cvta_generic_to_shared(dst);
    asm volatile("cp.async.cg.shared.global [%0], [%1], 16;\n" :: "r"(d), "l"(src));
}
__device__ __forceinline__ void cp_commit() { asm volatile("cp.async.commit_group;\n"); }
template<int N> __device__ __forceinline__ void cp_wait() {
    asm volatile("cp.async.wait_group %0;\n" :: "n"(N));
}

__device__ __forceinline__ void split2(float v, bf16& h, bf16& l) {
    h = __float2bfloat16(v);
    l = __float2bfloat16(v - __bfloat162float(h));
}

// exp2 on the FMA pipe (MUFU on B300 is only 0.5/cyc/SM)
__device__ __forceinline__ float fast_exp2(float y) {
    y = fmaxf(y, -120.f);
    float t = y + 12582912.f;
    int   yi = __float_as_int(t) - 0x4B400000;
    float f  = y - (t - 12582912.f);
    float p = 1.3333558146e-3f;
    p = fmaf(p, f, 9.6181291076e-3f);
    p = fmaf(p, f, 5.5504108664e-2f);
    p = fmaf(p, f, 2.4022650696e-1f);
    p = fmaf(p, f, 6.9314718056e-1f);
    p = fmaf(p, f, 1.0f);
    return p * __int_as_float((yi + 127) << 23);
}

__device__ __forceinline__ void pack_split(float a, float b, uint32_t& ph, uint32_t& pl) {
    bf16 ah, al, bh, bl;
    split2(a, ah, al); split2(b, bh, bl);
    __nv_bfloat162 Hh; Hh.x = ah; Hh.y = bh;
    __nv_bfloat162 Ll; Ll.x = al; Ll.y = bl;
    ph = *(uint32_t*)&Hh; pl = *(uint32_t*)&Ll;
}

// ---------------- prep kernels -------------------------------------------
__global__ __launch_bounds__(256) void split_x_kernel(const float* __restrict__ x) {
    size_t i = ((size_t)blockIdx.x * 256 + threadIdx.x) * 4;
    float4 v = *(const float4*)(x + i);
    bf16 h0,l0,h1,l1,h2,l2,h3,l3;
    split2(v.x,h0,l0); split2(v.y,h1,l1); split2(v.z,h2,l2); split2(v.w,h3,l3);
    __nv_bfloat162 a,b,c,d;
    a.x=h0; a.y=h1; b.x=h2; b.y=h3; c.x=l0; c.y=l1; d.x=l2; d.y=l3;
    *(__nv_bfloat162*)(g_xh + i)     = a;
    *(__nv_bfloat162*)(g_xh + i + 2) = b;
    *(__nv_bfloat162*)(g_xl + i)     = c;
    *(__nv_bfloat162*)(g_xl + i + 2) = d;
}

__global__ __launch_bounds__(256) void tsplit_kernel(const float* __restrict__ w,
                                                     int K, int N, int mode) {
    __shared__ float tile[32][33];
    bf16* outh = mode == 0 ? g_wqkvT_h : g_wpT_h;
    bf16* outl = mode == 0 ? g_wqkvT_l : g_wpT_l;
    const int n0 = blockIdx.x * 32, k0 = blockIdx.y * 32;
    const int tx = threadIdx.x & 31, ty = threadIdx.x >> 5;
#pragma unroll
    for (int r = 0; r < 32; r += 8)
        tile[ty + r][tx] = w[(size_t)(k0 + ty + r) * N + n0 + tx];
    __syncthreads();
#pragma unroll
    for (int r = 0; r < 32; r += 8) {
        float v = tile[tx][ty + r];
        bf16 h, l; split2(v, h, l);
        size_t o = (size_t)(n0 + ty + r) * K + k0 + tx;
        outh[o] = h; outl[o] = l;
    }
}

// ---------------- GEMM ----------------------------------------------------
__device__ __forceinline__ void epi_qkv(int m, int n, float v0, float v1) {
    const int b = m >> 12, t = m & 4095;
    const int sec = n / C_, r = n - sec * C_;
    const int h = r >> 6, d = r & 63;
    const int bh = b * H_ + h;
    if (sec == 2) {                        // V: fp16 single, transposed [bh][d][t]
        size_t o = ((size_t)bh * D_ + d) * T_ + t;
        g_Vt[o]      = __float2half(v0);
        g_Vt[o + T_] = __float2half(v1);
    } else {
        bf16 h0, l0, h1, l1;
        split2(v0, h0, l0); split2(v1, h1, l1);
        size_t o = ((size_t)bh * T_ + t) * D_ + d;
        bf16* dh = sec == 0 ? g_Qh : g_Kh;
        bf16* dl = sec == 0 ? g_Ql : g_Kl;
        __nv_bfloat162 Hh; Hh.x = h0; Hh.y = h1;
        __nv_bfloat162 Ll; Ll.x = l0; Ll.y = l1;
        *(__nv_bfloat162*)(dh + o) = Hh;
        *(__nv_bfloat162*)(dl + o) = Ll;
    }
}

template<int MODE>
__global__ __launch_bounds__(256, 2) void gemm_kernel(float* __restrict__ out) {
    extern __shared__ bf16 sm[];
    bf16* sAh = sm;
    bf16* sAl = sm + 2 * 5120;
    bf16* sBh = sm + 4 * 5120;
    bf16* sBl = sm + 6 * 5120;

    const bf16* Agh = (MODE == 1) ? g_xh : g_Yh;
    const bf16* Agl = (MODE == 1) ? g_xl : g_Yl;
    const bf16* Bgh = (MODE == 1) ? g_wqkvT_h : g_wpT_h;
    const bf16* Bgl = (MODE == 1) ? g_wqkvT_l : g_wpT_l;

    const int tid = threadIdx.x, wid = tid >> 5, lane = tid & 31;
    const int wm = wid >> 1, wn = wid & 1;
    const int lq = lane >> 2, cq = (lane & 3) << 1;
    const int bm = blockIdx.y * 128, bn = blockIdx.x * 128;

    float acc[2][8][4];
#pragma unroll
    for (int i = 0; i < 2; i++)
#pragma unroll
        for (int j = 0; j < 8; j++)
#pragma unroll
            for (int k = 0; k < 4; k++) acc[i][j][k] = 0.f;

#define LOAD_TILES(BUF, K0)                                                   \
    {                                                                         \
        _Pragma("unroll")                                                     \
        for (int i_ = 0; i_ < 2; i_++) {                                      \
            int c_ = tid + 256 * i_;                                          \
            int row_ = c_ >> 2;                                               \
            int ko_ = (c_ & 3) << 3;                                          \
            size_t ga_ = (size_t)(bm + row_) * C_ + (K0) + ko_;               \
            size_t gb_ = (size_t)(bn + row_) * C_ + (K0) + ko_;               \
            int so_ = (BUF) * 5120 + row_ * 40 + ko_;                         \
            cp16(sAh + so_, Agh + ga_);                                       \
            cp16(sAl + so_, Agl + ga_);                                       \
            cp16(sBh + so_, Bgh + gb_);                                       \
            cp16(sBl + so_, Bgl + gb_);                                       \
        }                                                                     \
    }

    LOAD_TILES(0, 0); cp_commit();
    int buf = 0;
    for (int kt = 0; kt < 24; kt++) {
        if (kt < 23) { LOAD_TILES(buf ^ 1, (kt + 1) * 32); cp_commit(); cp_wait<1>(); }
        else cp_wait<0>();
        __syncthreads();
#pragma unroll
        for (int kc = 0; kc < 2; kc++) {
            const int ko = kc * 16 + cq;
            uint32_t ah[2][4], al[2][4];
#pragma unroll
            for (int mc = 0; mc < 2; mc++) {
                const bf16* p = sAh + buf * 5120 + (wm * 32 + mc * 16 + lq) * 40 + ko;
                ah[mc][0] = *(const uint32_t*)p;
                ah[mc][1] = *(const uint32_t*)(p + 8 * 40);
                ah[mc][2] = *(const uint32_t*)(p + 8);
                ah[mc][3] = *(const uint32_t*)(p + 8 * 40 + 8);
                const bf16* q = sAl + buf * 5120 + (wm * 32 + mc * 16 + lq) * 40 + ko;
                al[mc][0] = *(const uint32_t*)q;
                al[mc][1] = *(const uint32_t*)(q + 8 * 40);
                al[mc][2] = *(const uint32_t*)(q + 8);
                al[mc][3] = *(const uint32_t*)(q + 8 * 40 + 8);
            }
#pragma unroll
            for (int nc = 0; nc < 8; nc++) {
                const bf16* p = sBh + buf * 5120 + (wn * 64 + nc * 8 + lq) * 40 + ko;
                uint32_t bh2[2] = { *(const uint32_t*)p, *(const uint32_t*)(p + 8) };
                const bf16* q = sBl + buf * 5120 + (wn * 64 + nc * 8 + lq) * 40 + ko;
                uint32_t bl2[2] = { *(const uint32_t*)q, *(const uint32_t*)(q + 8) };
#pragma unroll
                for (int mc = 0; mc < 2; mc++) {
                    mma16816(acc[mc][nc], ah[mc], bh2);
                    mma16816(acc[mc][nc], ah[mc], bl2);
                    mma16816(acc[mc][nc], al[mc], bh2);
                }
            }
        }
        __syncthreads();
        buf ^= 1;
    }

#pragma unroll
    for (int mc = 0; mc < 2; mc++)
#pragma unroll
        for (int nc = 0; nc < 8; nc++) {
            const int m = bm + wm * 32 + mc * 16 + lq;
            const int n = bn + wn * 64 + nc * 8 + cq;
            float* a = acc[mc][nc];
            if (MODE == 2) {
                *(float2*)&out[(size_t)m * C_ + n]       = make_float2(a[0], a[1]);
                *(float2*)&out[(size_t)(m + 8) * C_ + n] = make_float2(a[2], a[3]);
            } else {
                epi_qkv(m, n, a[0], a[1]);
                epi_qkv(m + 8, n, a[2], a[3]);
            }
        }
}

// ---------------- flash attention -----------------------------------------
#define SA_ 0.1803368801111204f     /* 0.125 * log2(e) */
#define FSTAGE 13824                /* (sKh + sKl + sVt) elems of 2B per stage */
#define FLASH_SMEM (2 * FSTAGE * 2)

__global__ __launch_bounds__(256) void flash_kernel() {
    extern __shared__ bf16 fsm[];

    const int qt = (int)(gridDim.x - 1) - (int)blockIdx.x;   // heavy tiles first
    const int bh = blockIdx.y;
    const int tid = threadIdx.x, wid = tid >> 5, lane = tid & 31;
    const int lq = lane >> 2, cq = (lane & 3) << 1;
    const int row0 = qt * 128 + wid * 16 + lq;

    // Q fragments, register resident
    const size_t qoff = ((size_t)bh * T_ + row0) * D_;
    uint32_t qh[4][4], ql[4][4];
#pragma unroll
    for (int kc = 0; kc < 4; kc++) {
        const int c = kc * 16 + cq;
        qh[kc][0] = *(const uint32_t*)(g_Qh + qoff + c);
        qh[kc][1] = *(const uint32_t*)(g_Qh + qoff + 8 * D_ + c);
        qh[kc][2] = *(const uint32_t*)(g_Qh + qoff + c + 8);
        qh[kc][3] = *(const uint32_t*)(g_Qh + qoff + 8 * D_ + c + 8);
        ql[kc][0] = *(const uint32_t*)(g_Ql + qoff + c);
        ql[kc][1] = *(const uint32_t*)(g_Ql + qoff + 8 * D_ + c);
        ql[kc][2] = *(const uint32_t*)(g_Ql + qoff + c + 8);
        ql[kc][3] = *(const uint32_t*)(g_Ql + qoff + 8 * D_ + c + 8);
    }

    float oacc[8][4];
#pragma unroll
    for (int i = 0; i < 8; i++)
#pragma unroll
        for (int j = 0; j < 4; j++) oacc[i][j] = 0.f;
    float m0 = -1e30f, m1 = -1e30f, l0 = 0.f, l1 = 0.f;

    const bf16* Kb_h = g_Kh + (size_t)bh * T_ * D_;
    const bf16* Kb_l = g_Kl + (size_t)bh * T_ * D_;
    const __half* Vb = g_Vt + (size_t)bh * D_ * T_;

#define LOADF(BUF, KT)                                                        \
    {                                                                         \
        bf16* bb = fsm + (BUF) * FSTAGE;                                      \
        const bf16* ph_ = Kb_h + (size_t)(KT) * 64 * D_;                      \
        const bf16* pl_ = Kb_l + (size_t)(KT) * 64 * D_;                      \
        _Pragma("unroll")                                                     \
        for (int c_ = tid; c_ < 512; c_ += 256) {                             \
            const int r_ = c_ >> 3, of_ = (c_ & 7) << 3;                      \
            cp16(bb + r_ * 72 + of_, ph_ + r_ * D_ + of_);                    \
            cp16(bb + 4608 + r_ * 72 + of_, pl_ + r_ * D_ + of_);             \
            cp16((__half*)(bb + 9216) + r_ * 72 + of_,                        \
                 Vb + (size_t)r_ * T_ + (KT) * 64 + of_);                     \
        }                                                                     \
    }

    const int nkt = 2 * qt + 2;
    LOADF(0, 0); cp_commit();
    int buf = 0;
    for (int kt = 0; kt < nkt; kt++) {
        cp_wait<0>(); __syncthreads();
        if (kt + 1 < nkt) { LOADF(buf ^ 1, kt + 1); cp_commit(); }

        const bf16* sKh = fsm + buf * FSTAGE;
        const bf16* sKl = sKh + 4608;
        const __half* sVt = (const __half*)(sKh + 9216);

        // S = Q K^T (3-term bf16 split)
        float sacc[8][4];
#pragma unroll
        for (int i = 0; i < 8; i++)
#pragma unroll
            for (int j = 0; j < 4; j++) sacc[i][j] = 0.f;
#pragma unroll
        for (int kc = 0; kc < 4; kc++) {
            const int ko = kc * 16 + cq;
#pragma unroll
            for (int nc = 0; nc < 8; nc++) {
                const bf16* p = sKh + (nc * 8 + lq) * 72 + ko;
                uint32_t bh2[2] = { *(const uint32_t*)p, *(const uint32_t*)(p + 8) };
                const bf16* q = sKl + (nc * 8 + lq) * 72 + ko;
                uint32_t bl2[2] = { *(const uint32_t*)q, *(const uint32_t*)(q + 8) };
                mma16816(sacc[nc], qh[kc], bh2);
                mma16816(sacc[nc], qh[kc], bl2);
                mma16816(sacc[nc], ql[kc], bh2);
            }
        }

        // causal mask
        if (kt >= 2 * qt) {
            const int colb = kt * 64;
#pragma unroll
            for (int nc = 0; nc < 8; nc++) {
                const int c0 = colb + nc * 8 + cq;
                if (c0     > row0)     sacc[nc][0] = -1e30f;
                if (c0 + 1 > row0)     sacc[nc][1] = -1e30f;
                if (c0     > row0 + 8) sacc[nc][2] = -1e30f;
                if (c0 + 1 > row0 + 8) sacc[nc][3] = -1e30f;
            }
        }

        // online softmax
        float mx0 = -1e30f, mx1 = -1e30f;
#pragma unroll
        for (int nc = 0; nc < 8; nc++) {
            mx0 = fmaxf(mx0, fmaxf(sacc[nc][0], sacc[nc][1]));
            mx1 = fmaxf(mx1, fmaxf(sacc[nc][2], sacc[nc][3]));
        }
        mx0 = fmaxf(mx0, __shfl_xor_sync(0xffffffffu, mx0, 1));
        mx0 = fmaxf(mx0, __shfl_xor_sync(0xffffffffu, mx0, 2));
        mx1 = fmaxf(mx1, __shfl_xor_sync(0xffffffffu, mx1, 1));
        mx1 = fmaxf(mx1, __shfl_xor_sync(0xffffffffu, mx1, 2));
        const float mn0 = fmaxf(m0, mx0), mn1 = fmaxf(m1, mx1);
        const float sc0 = fast_exp2((m0 - mn0) * SA_);
        const float sc1 = fast_exp2((m1 - mn1) * SA_);
        m0 = mn0; m1 = mn1;
        l0 *= sc0; l1 *= sc1;
#pragma unroll
        for (int dc = 0; dc < 8; dc++) {
            oacc[dc][0] *= sc0; oacc[dc][1] *= sc0;
            oacc[dc][2] *= sc1; oacc[dc][3] *= sc1;
        }

        // P = exp(S - m), packed as fp16 A-fragments (single precision term)
        uint32_t pa[4][4];
#pragma unroll
        for (int kc = 0; kc < 4; kc++) {
            const float e0 = fast_exp2((sacc[2*kc][0]   - m0) * SA_);
            const float e1 = fast_exp2((sacc[2*kc][1]   - m0) * SA_);
            const float e2 = fast_exp2((sacc[2*kc][2]   - m1) * SA_);
            const float e3 = fast_exp2((sacc[2*kc][3]   - m1) * SA_);
            const float f0 = fast_exp2((sacc[2*kc+1][0] - m0) * SA_);
            const float f1 = fast_exp2((sacc[2*kc+1][1] - m0) * SA_);
            const float f2 = fast_exp2((sacc[2*kc+1][2] - m1) * SA_);
            const float f3 = fast_exp2((sacc[2*kc+1][3] - m1) * SA_);
            l0 += e0 + e1 + f0 + f1;
            l1 += e2 + e3 + f2 + f3;
            __half2 t0 = __floats2half2_rn(e0, e1);
            __half2 t1 = __floats2half2_rn(e2, e3);
            __half2 t2 = __floats2half2_rn(f0, f1);
            __half2 t3 = __floats2half2_rn(f2, f3);
            pa[kc][0] = *(uint32_t*)&t0;
            pa[kc][1] = *(uint32_t*)&t1;
            pa[kc][2] = *(uint32_t*)&t2;
            pa[kc][3] = *(uint32_t*)&t3;
        }

        // O += P V  (single fp16 mma)
#pragma unroll
        for (int kc = 0; kc < 4; kc++) {
            const int ko = kc * 16 + cq;
#pragma unroll
            for (int dc = 0; dc < 8; dc++) {
                const __half* p = sVt + (dc * 8 + lq) * 72 + ko;
                uint32_t v2[2] = { *(const uint32_t*)p, *(const uint32_t*)(p + 8) };
                mma16816h(oacc[dc], pa[kc], v2);
            }
        }
        __syncthreads();
        buf ^= 1;
    }

    // finalize
    l0 += __shfl_xor_sync(0xffffffffu, l0, 1);
    l0 += __shfl_xor_sync(0xffffffffu, l0, 2);
    l1 += __shfl_xor_sync(0xffffffffu, l1, 1);
    l1 += __shfl_xor_sync(0xffffffffu, l1, 2);
    const float inv0 = 1.f / l0, inv1 = 1.f / l1;

    const int b = bh / H_, h = bh - b * H_;
    const size_t y0 = ((size_t)b * T_ + row0) * C_ + h * D_;
    const size_t y1 = ((size_t)b * T_ + row0 + 8) * C_ + h * D_;
#pragma unroll
    for (int dc = 0; dc < 8; dc++) {
        const int col = dc * 8 + cq;
        uint32_t ph, pl;
        pack_split(oacc[dc][0] * inv0, oacc[dc][1] * inv0, ph, pl);
        *(uint32_t*)(g_Yh + y0 + col) = ph;
        *(uint32_t*)(g_Yl + y0 + col) = pl;
        pack_split(oacc[dc][2] * inv1, oacc[dc][3] * inv1, ph, pl);
        *(uint32_t*)(g_Yh + y1 + col) = ph;
        *(uint32_t*)(g_Yl + y1 + col) = pl;
    }
}

// ---------------------------------------------------------------------------
extern "C" void kernel_launch(void* const* d_in, const int* in_sizes, int n_in,
                              void* d_out, int out_size)
{
    const float* x      = (const float*)d_in[0];
    const float* w_qkv  = (const float*)d_in[1];
    const float* w_proj = (const float*)d_in[2];
    float* out = (float*)d_out;

    split_x_kernel<<<(M_ * C_) / (256 * 4), 256>>>(x);
    tsplit_kernel<<<dim3(NQKV_ / 32, C_ / 32), 256>>>(w_qkv, C_, NQKV_, 0);
    tsplit_kernel<<<dim3(C_ / 32, C_ / 32), 256>>>(w_proj, C_, C_, 1);

    const int gsmem = 8 * 5120 * (int)sizeof(bf16);   // 80 KB
    cudaFuncSetAttribute(gemm_kernel<1>, cudaFuncAttributeMaxDynamicSharedMemorySize, gsmem);
    cudaFuncSetAttribute(gemm_kernel<2>, cudaFuncAttributeMaxDynamicSharedMemorySize, gsmem);
    const int fsmem = FLASH_SMEM;                      // 54 KB
    cudaFuncSetAttribute(flash_kernel, cudaFuncAttributeMaxDynamicSharedMemorySize, fsmem);

    gemm_kernel<1><<<dim3(NQKV_ / 128, M_ / 128), 256, gsmem>>>(nullptr);
    flash_kernel<<<dim3(T_ / 128, BH_), 256, fsmem>>>();
    gemm_kernel<2><<<dim3(C_ / 128, M_ / 128), 256, gsmem>>>(out);
}

// round 4
// speedup vs baseline: 5.2191x; 1.0554x over previous
#include <cuda_runtime.h>
#include <cuda_bf16.h>
#include <cuda_fp16.h>
#include <math.h>
#include <stdint.h>

#define B_  2
#define T_  4096
#define C_  768
#define H_  12
#define D_  64
#define NQKV_ 2304
#define M_  8192
#define BH_ (B_*H_)

typedef __nv_bfloat16 bf16;

// ---------------- device scratch (allocation-free rule) -------------------
__device__ __align__(16) bf16 g_xh[M_*C_],      g_xl[M_*C_];
__device__ __align__(16) bf16 g_wqkvT_h[NQKV_*C_], g_wqkvT_l[NQKV_*C_];
__device__ __align__(16) bf16 g_wpT_h[C_*C_],   g_wpT_l[C_*C_];
__device__ __align__(16) bf16 g_Qh[BH_*T_*D_],  g_Ql[BH_*T_*D_];
__device__ __align__(16) bf16 g_Kh[BH_*T_*D_],  g_Kl[BH_*T_*D_];
__device__ __align__(16) __half g_Vt[BH_*D_*T_];          // [bh][d][t], single fp16
__device__ __align__(16) bf16 g_Yh[M_*C_],      g_Yl[M_*C_];

// ---------------- helpers -------------------------------------------------
__device__ __forceinline__ void mma16816(float c[4], const uint32_t a[4], const uint32_t b[2]) {
    asm volatile("mma.sync.aligned.m16n8k16.row.col.f32.bf16.bf16.f32 "
        "{%0,%1,%2,%3}, {%4,%5,%6,%7}, {%8,%9}, {%0,%1,%2,%3};\n"
        : "+f"(c[0]), "+f"(c[1]), "+f"(c[2]), "+f"(c[3])
        : "r"(a[0]), "r"(a[1]), "r"(a[2]), "r"(a[3]), "r"(b[0]), "r"(b[1]));
}
__device__ __forceinline__ void mma16816h(float c[4], const uint32_t a[4], const uint32_t b[2]) {
    asm volatile("mma.sync.aligned.m16n8k16.row.col.f32.f16.f16.f32 "
        "{%0,%1,%2,%3}, {%4,%5,%6,%7}, {%8,%9}, {%0,%1,%2,%3};\n"
        : "+f"(c[0]), "+f"(c[1]), "+f"(c[2]), "+f"(c[3])
        : "r"(a[0]), "r"(a[1]), "r"(a[2]), "r"(a[3]), "r"(b[0]), "r"(b[1]));
}
// warp-collective: 4x (8x8 b16) tiles, per-lane address
__device__ __forceinline__ void ldsm4(uint32_t r[4], const void* p) {
    uint32_t a = (uint32_t)__cvta_generic_to_shared(p);
    asm volatile("ldmatrix.sync.aligned.m8n8.x4.shared.b16 {%0,%1,%2,%3}, [%4];"
        : "=r"(r[0]), "=r"(r[1]), "=r"(r[2]), "=r"(r[3]) : "r"(a));
}

__device__ __forceinline__ void cp16(void* dst, const void* src) {
    unsigned d = (unsigned)__cvta_generic_to_shared(dst);
    asm volatile("cp.async.cg.shared.global [%0], [%1], 16;\n" :: "r"(d), "l"(src));
}
__device__ __forceinline__ void cp_commit() { asm volatile("cp.async.commit_group;\n"); }
template<int N> __device__ __forceinline__ void cp_wait() {
    asm volatile("cp.async.wait_group %0;\n" :: "n"(N));
}

__device__ __forceinline__ void split2(float v, bf16& h, bf16& l) {
    h = __float2bfloat16(v);
    l = __float2bfloat16(v - __bfloat162float(h));
}

__device__ __forceinline__ float fast_exp2(float y) {
    y = fmaxf(y, -120.f);
    float t = y + 12582912.f;
    int   yi = __float_as_int(t) - 0x4B400000;
    float f  = y - (t - 12582912.f);
    float p = 1.3333558146e-3f;
    p = fmaf(p, f, 9.6181291076e-3f);
    p = fmaf(p, f, 5.5504108664e-2f);
    p = fmaf(p, f, 2.4022650696e-1f);
    p = fmaf(p, f, 6.9314718056e-1f);
    p = fmaf(p, f, 1.0f);
    return p * __int_as_float((yi + 127) << 23);
}

__device__ __forceinline__ void pack_split(float a, float b, uint32_t& ph, uint32_t& pl) {
    bf16 ah, al, bh, bl;
    split2(a, ah, al); split2(b, bh, bl);
    __nv_bfloat162 Hh; Hh.x = ah; Hh.y = bh;
    __nv_bfloat162 Ll; Ll.x = al; Ll.y = bl;
    ph = *(uint32_t*)&Hh; pl = *(uint32_t*)&Ll;
}

// ---------------- prep kernels -------------------------------------------
__global__ __launch_bounds__(256) void split_x_kernel(const float* __restrict__ x) {
    size_t i = ((size_t)blockIdx.x * 256 + threadIdx.x) * 4;
    float4 v = *(const float4*)(x + i);
    bf16 h0,l0,h1,l1,h2,l2,h3,l3;
    split2(v.x,h0,l0); split2(v.y,h1,l1); split2(v.z,h2,l2); split2(v.w,h3,l3);
    __nv_bfloat162 a,b,c,d;
    a.x=h0; a.y=h1; b.x=h2; b.y=h3; c.x=l0; c.y=l1; d.x=l2; d.y=l3;
    *(__nv_bfloat162*)(g_xh + i)     = a;
    *(__nv_bfloat162*)(g_xh + i + 2) = b;
    *(__nv_bfloat162*)(g_xl + i)     = c;
    *(__nv_bfloat162*)(g_xl + i + 2) = d;
}

__global__ __launch_bounds__(256) void tsplit_kernel(const float* __restrict__ w,
                                                     int K, int N, int mode) {
    __shared__ float tile[32][33];
    bf16* outh = mode == 0 ? g_wqkvT_h : g_wpT_h;
    bf16* outl = mode == 0 ? g_wqkvT_l : g_wpT_l;
    const int n0 = blockIdx.x * 32, k0 = blockIdx.y * 32;
    const int tx = threadIdx.x & 31, ty = threadIdx.x >> 5;
#pragma unroll
    for (int r = 0; r < 32; r += 8)
        tile[ty + r][tx] = w[(size_t)(k0 + ty + r) * N + n0 + tx];
    __syncthreads();
#pragma unroll
    for (int r = 0; r < 32; r += 8) {
        float v = tile[tx][ty + r];
        bf16 h, l; split2(v, h, l);
        size_t o = (size_t)(n0 + ty + r) * K + k0 + tx;
        outh[o] = h; outl[o] = l;
    }
}

// ---------------- GEMM ----------------------------------------------------
__device__ __forceinline__ void epi_qkv(int m, int n, float v0, float v1) {
    const int b = m >> 12, t = m & 4095;
    const int sec = n / C_, r = n - sec * C_;
    const int h = r >> 6, d = r & 63;
    const int bh = b * H_ + h;
    if (sec == 2) {
        size_t o = ((size_t)bh * D_ + d) * T_ + t;
        g_Vt[o]      = __float2half(v0);
        g_Vt[o + T_] = __float2half(v1);
    } else {
        bf16 h0, l0, h1, l1;
        split2(v0, h0, l0); split2(v1, h1, l1);
        size_t o = ((size_t)bh * T_ + t) * D_ + d;
        bf16* dh = sec == 0 ? g_Qh : g_Kh;
        bf16* dl = sec == 0 ? g_Ql : g_Kl;
        __nv_bfloat162 Hh; Hh.x = h0; Hh.y = h1;
        __nv_bfloat162 Ll; Ll.x = l0; Ll.y = l1;
        *(__nv_bfloat162*)(dh + o) = Hh;
        *(__nv_bfloat162*)(dl + o) = Ll;
    }
}

template<int MODE>
__global__ __launch_bounds__(256, 2) void gemm_kernel(float* __restrict__ out) {
    extern __shared__ bf16 sm[];
    bf16* sAh = sm;
    bf16* sAl = sm + 2 * 5120;
    bf16* sBh = sm + 4 * 5120;
    bf16* sBl = sm + 6 * 5120;

    const bf16* Agh = (MODE == 1) ? g_xh : g_Yh;
    const bf16* Agl = (MODE == 1) ? g_xl : g_Yl;
    const bf16* Bgh = (MODE == 1) ? g_wqkvT_h : g_wpT_h;
    const bf16* Bgl = (MODE == 1) ? g_wqkvT_l : g_wpT_l;

    const int tid = threadIdx.x, wid = tid >> 5, lane = tid & 31;
    const int wm = wid >> 1, wn = wid & 1;
    const int lq = lane >> 2, cq = (lane & 3) << 1;
    const int bm = blockIdx.y * 128, bn = blockIdx.x * 128;

    // per-lane ldmatrix offsets (elements)
    const int a_loff = ((((lane >> 3) & 1) * 8 + (lane & 7)) * 40) + (lane >> 4) * 8;
    const int b_loff = (((lane >> 4) * 8 + (lane & 7)) * 40) + ((lane >> 3) & 1) * 8;

    float acc[2][8][4];
#pragma unroll
    for (int i = 0; i < 2; i++)
#pragma unroll
        for (int j = 0; j < 8; j++)
#pragma unroll
            for (int k = 0; k < 4; k++) acc[i][j][k] = 0.f;

#define LOAD_TILES(BUF, K0)                                                   \
    {                                                                         \
        _Pragma("unroll")                                                     \
        for (int i_ = 0; i_ < 2; i_++) {                                      \
            int c_ = tid + 256 * i_;                                          \
            int row_ = c_ >> 2;                                               \
            int ko_ = (c_ & 3) << 3;                                          \
            size_t ga_ = (size_t)(bm + row_) * C_ + (K0) + ko_;               \
            size_t gb_ = (size_t)(bn + row_) * C_ + (K0) + ko_;               \
            int so_ = (BUF) * 5120 + row_ * 40 + ko_;                         \
            cp16(sAh + so_, Agh + ga_);                                       \
            cp16(sAl + so_, Agl + ga_);                                       \
            cp16(sBh + so_, Bgh + gb_);                                       \
            cp16(sBl + so_, Bgl + gb_);                                       \
        }                                                                     \
    }

    LOAD_TILES(0, 0); cp_commit();
    int buf = 0;
    for (int kt = 0; kt < 24; kt++) {
        if (kt < 23) { LOAD_TILES(buf ^ 1, (kt + 1) * 32); cp_commit(); cp_wait<1>(); }
        else cp_wait<0>();
        __syncthreads();
#pragma unroll
        for (int kc = 0; kc < 2; kc++) {
            uint32_t ah[2][4], al[2][4];
#pragma unroll
            for (int mc = 0; mc < 2; mc++) {
                const int ao = buf * 5120 + (wm * 32 + mc * 16) * 40 + kc * 16 + a_loff;
                ldsm4(ah[mc], sAh + ao);
                ldsm4(al[mc], sAl + ao);
            }
#pragma unroll
            for (int nc2 = 0; nc2 < 4; nc2++) {
                uint32_t bh4[4], bl4[4];
                const int bo = buf * 5120 + (wn * 64 + nc2 * 16) * 40 + kc * 16 + b_loff;
                ldsm4(bh4, sBh + bo);
                ldsm4(bl4, sBl + bo);
#pragma unroll
                for (int mc = 0; mc < 2; mc++) {
                    mma16816(acc[mc][2*nc2],   ah[mc], &bh4[0]);
                    mma16816(acc[mc][2*nc2],   ah[mc], &bl4[0]);
                    mma16816(acc[mc][2*nc2],   al[mc], &bh4[0]);
                    mma16816(acc[mc][2*nc2+1], ah[mc], &bh4[2]);
                    mma16816(acc[mc][2*nc2+1], ah[mc], &bl4[2]);
                    mma16816(acc[mc][2*nc2+1], al[mc], &bh4[2]);
                }
            }
        }
        __syncthreads();
        buf ^= 1;
    }

#pragma unroll
    for (int mc = 0; mc < 2; mc++)
#pragma unroll
        for (int nc = 0; nc < 8; nc++) {
            const int m = bm + wm * 32 + mc * 16 + lq;
            const int n = bn + wn * 64 + nc * 8 + cq;
            float* a = acc[mc][nc];
            if (MODE == 2) {
                *(float2*)&out[(size_t)m * C_ + n]       = make_float2(a[0], a[1]);
                *(float2*)&out[(size_t)(m + 8) * C_ + n] = make_float2(a[2], a[3]);
            } else {
                epi_qkv(m, n, a[0], a[1]);
                epi_qkv(m + 8, n, a[2], a[3]);
            }
        }
}

// ---------------- flash attention -----------------------------------------
#define SA_ 0.1803368801111204f     /* 0.125 * log2(e) */
#define FSTAGE 13824
#define FLASH_SMEM (2 * FSTAGE * 2)

__global__ __launch_bounds__(256) void flash_kernel() {
    extern __shared__ bf16 fsm[];

    const int qt = (int)(gridDim.x - 1) - (int)blockIdx.x;
    const int bh = blockIdx.y;
    const int tid = threadIdx.x, wid = tid >> 5, lane = tid & 31;
    const int lq = lane >> 2, cq = (lane & 3) << 1;
    const int row0 = qt * 128 + wid * 16 + lq;

    // per-lane ldmatrix offset for B-style fragments, stride 72
    const int b_loff = (((lane >> 4) * 8 + (lane & 7)) * 72) + ((lane >> 3) & 1) * 8;

    const size_t qoff = ((size_t)bh * T_ + row0) * D_;
    uint32_t qh[4][4], ql[4][4];
#pragma unroll
    for (int kc = 0; kc < 4; kc++) {
        const int c = kc * 16 + cq;
        qh[kc][0] = *(const uint32_t*)(g_Qh + qoff + c);
        qh[kc][1] = *(const uint32_t*)(g_Qh + qoff + 8 * D_ + c);
        qh[kc][2] = *(const uint32_t*)(g_Qh + qoff + c + 8);
        qh[kc][3] = *(const uint32_t*)(g_Qh + qoff + 8 * D_ + c + 8);
        ql[kc][0] = *(const uint32_t*)(g_Ql + qoff + c);
        ql[kc][1] = *(const uint32_t*)(g_Ql + qoff + 8 * D_ + c);
        ql[kc][2] = *(const uint32_t*)(g_Ql + qoff + c + 8);
        ql[kc][3] = *(const uint32_t*)(g_Ql + qoff + 8 * D_ + c + 8);
    }

    float oacc[8][4];
#pragma unroll
    for (int i = 0; i < 8; i++)
#pragma unroll
        for (int j = 0; j < 4; j++) oacc[i][j] = 0.f;
    float m0 = -1e30f, m1 = -1e30f, l0 = 0.f, l1 = 0.f;

    const bf16* Kb_h = g_Kh + (size_t)bh * T_ * D_;
    const bf16* Kb_l = g_Kl + (size_t)bh * T_ * D_;
    const __half* Vb = g_Vt + (size_t)bh * D_ * T_;

#define LOADF(BUF, KT)                                                        \
    {                                                                         \
        bf16* bb = fsm + (BUF) * FSTAGE;                                      \
        const bf16* ph_ = Kb_h + (size_t)(KT) * 64 * D_;                      \
        const bf16* pl_ = Kb_l + (size_t)(KT) * 64 * D_;                      \
        _Pragma("unroll")                                                     \
        for (int c_ = tid; c_ < 512; c_ += 256) {                             \
            const int r_ = c_ >> 3, of_ = (c_ & 7) << 3;                      \
            cp16(bb + r_ * 72 + of_, ph_ + r_ * D_ + of_);                    \
            cp16(bb + 4608 + r_ * 72 + of_, pl_ + r_ * D_ + of_);             \
            cp16((__half*)(bb + 9216) + r_ * 72 + of_,                        \
                 Vb + (size_t)r_ * T_ + (KT) * 64 + of_);                     \
        }                                                                     \
    }

    const int nkt = 2 * qt + 2;
    LOADF(0, 0); cp_commit();
    int buf = 0;
    for (int kt = 0; kt < nkt; kt++) {
        cp_wait<0>(); __syncthreads();
        if (kt + 1 < nkt) { LOADF(buf ^ 1, kt + 1); cp_commit(); }

        const bf16* sKh = fsm + buf * FSTAGE;
        const bf16* sKl = sKh + 4608;
        const __half* sVt = (const __half*)(sKh + 9216);

        // S = Q K^T (3-term bf16 split), fragments via ldmatrix
        float sacc[8][4];
#pragma unroll
        for (int i = 0; i < 8; i++)
#pragma unroll
            for (int j = 0; j < 4; j++) sacc[i][j] = 0.f;
#pragma unroll
        for (int kc = 0; kc < 4; kc++) {
#pragma unroll
            for (int nc2 = 0; nc2 < 4; nc2++) {
                uint32_t kh4[4], kl4[4];
                const int o = nc2 * 16 * 72 + kc * 16 + b_loff;
                ldsm4(kh4, sKh + o);
                ldsm4(kl4, sKl + o);
                mma16816(sacc[2*nc2],   qh[kc], &kh4[0]);
                mma16816(sacc[2*nc2],   qh[kc], &kl4[0]);
                mma16816(sacc[2*nc2],   ql[kc], &kh4[0]);
                mma16816(sacc[2*nc2+1], qh[kc], &kh4[2]);
                mma16816(sacc[2*nc2+1], qh[kc], &kl4[2]);
                mma16816(sacc[2*nc2+1], ql[kc], &kh4[2]);
            }
        }

        // causal mask
        if (kt >= 2 * qt) {
            const int colb = kt * 64;
#pragma unroll
            for (int nc = 0; nc < 8; nc++) {
                const int c0 = colb + nc * 8 + cq;
                if (c0     > row0)     sacc[nc][0] = -1e30f;
                if (c0 + 1 > row0)     sacc[nc][1] = -1e30f;
                if (c0     > row0 + 8) sacc[nc][2] = -1e30f;
                if (c0 + 1 > row0 + 8) sacc[nc][3] = -1e30f;
            }
        }

        // online softmax
        float mx0 = -1e30f, mx1 = -1e30f;
#pragma unroll
        for (int nc = 0; nc < 8; nc++) {
            mx0 = fmaxf(mx0, fmaxf(sacc[nc][0], sacc[nc][1]));
            mx1 = fmaxf(mx1, fmaxf(sacc[nc][2], sacc[nc][3]));
        }
        mx0 = fmaxf(mx0, __shfl_xor_sync(0xffffffffu, mx0, 1));
        mx0 = fmaxf(mx0, __shfl_xor_sync(0xffffffffu, mx0, 2));
        mx1 = fmaxf(mx1, __shfl_xor_sync(0xffffffffu, mx1, 1));
        mx1 = fmaxf(mx1, __shfl_xor_sync(0xffffffffu, mx1, 2));
        const float mn0 = fmaxf(m0, mx0), mn1 = fmaxf(m1, mx1);
        const float sc0 = fast_exp2((m0 - mn0) * SA_);
        const float sc1 = fast_exp2((m1 - mn1) * SA_);
        m0 = mn0; m1 = mn1;
        l0 *= sc0; l1 *= sc1;
#pragma unroll
        for (int dc = 0; dc < 8; dc++) {
            oacc[dc][0] *= sc0; oacc[dc][1] *= sc0;
            oacc[dc][2] *= sc1; oacc[dc][3] *= sc1;
        }

        // P = exp(S - m) -> fp16 A fragments
        uint32_t pa[4][4];
#pragma unroll
        for (int kc = 0; kc < 4; kc++) {
            const float e0 = fast_exp2((sacc[2*kc][0]   - m0) * SA_);
            const float e1 = fast_exp2((sacc[2*kc][1]   - m0) * SA_);
            const float e2 = fast_exp2((sacc[2*kc][2]   - m1) * SA_);
            const float e3 = fast_exp2((sacc[2*kc][3]   - m1) * SA_);
            const float f0 = fast_exp2((sacc[2*kc+1][0] - m0) * SA_);
            const float f1 = fast_exp2((sacc[2*kc+1][1] - m0) * SA_);
            const float f2 = fast_exp2((sacc[2*kc+1][2] - m1) * SA_);
            const float f3 = fast_exp2((sacc[2*kc+1][3] - m1) * SA_);
            l0 += e0 + e1 + f0 + f1;
            l1 += e2 + e3 + f2 + f3;
            __half2 t0 = __floats2half2_rn(e0, e1);
            __half2 t1 = __floats2half2_rn(e2, e3);
            __half2 t2 = __floats2half2_rn(f0, f1);
            __half2 t3 = __floats2half2_rn(f2, f3);
            pa[kc][0] = *(uint32_t*)&t0;
            pa[kc][1] = *(uint32_t*)&t1;
            pa[kc][2] = *(uint32_t*)&t2;
            pa[kc][3] = *(uint32_t*)&t3;
        }

        // O += P V  (single fp16 mma), V fragments via ldmatrix
#pragma unroll
        for (int kc = 0; kc < 4; kc++) {
#pragma unroll
            for (int dc2 = 0; dc2 < 4; dc2++) {
                uint32_t v4[4];
                ldsm4(v4, sVt + dc2 * 16 * 72 + kc * 16 + b_loff);
                mma16816h(oacc[2*dc2],   pa[kc], &v4[0]);
                mma16816h(oacc[2*dc2+1], pa[kc], &v4[2]);
            }
        }
        __syncthreads();
        buf ^= 1;
    }

    // finalize
    l0 += __shfl_xor_sync(0xffffffffu, l0, 1);
    l0 += __shfl_xor_sync(0xffffffffu, l0, 2);
    l1 += __shfl_xor_sync(0xffffffffu, l1, 1);
    l1 += __shfl_xor_sync(0xffffffffu, l1, 2);
    const float inv0 = 1.f / l0, inv1 = 1.f / l1;

    const int b = bh / H_, h = bh - b * H_;
    const size_t y0 = ((size_t)b * T_ + row0) * C_ + h * D_;
    const size_t y1 = ((size_t)b * T_ + row0 + 8) * C_ + h * D_;
#pragma unroll
    for (int dc = 0; dc < 8; dc++) {
        const int col = dc * 8 + cq;
        uint32_t ph, pl;
        pack_split(oacc[dc][0] * inv0, oacc[dc][1] * inv0, ph, pl);
        *(uint32_t*)(g_Yh + y0 + col) = ph;
        *(uint32_t*)(g_Yl + y0 + col) = pl;
        pack_split(oacc[dc][2] * inv1, oacc[dc][3] * inv1, ph, pl);
        *(uint32_t*)(g_Yh + y1 + col) = ph;
        *(uint32_t*)(g_Yl + y1 + col) = pl;
    }
}

// ---------------------------------------------------------------------------
extern "C" void kernel_launch(void* const* d_in, const int* in_sizes, int n_in,
                              void* d_out, int out_size)
{
    const float* x      = (const float*)d_in[0];
    const float* w_qkv  = (const float*)d_in[1];
    const float* w_proj = (const float*)d_in[2];
    float* out = (float*)d_out;

    split_x_kernel<<<(M_ * C_) / (256 * 4), 256>>>(x);
    tsplit_kernel<<<dim3(NQKV_ / 32, C_ / 32), 256>>>(w_qkv, C_, NQKV_, 0);
    tsplit_kernel<<<dim3(C_ / 32, C_ / 32), 256>>>(w_proj, C_, C_, 1);

    const int gsmem = 8 * 5120 * (int)sizeof(bf16);   // 80 KB
    cudaFuncSetAttribute(gemm_kernel<1>, cudaFuncAttributeMaxDynamicSharedMemorySize, gsmem);
    cudaFuncSetAttribute(gemm_kernel<2>, cudaFuncAttributeMaxDynamicSharedMemorySize, gsmem);
    const int fsmem = FLASH_SMEM;                      // 54 KB
    cudaFuncSetAttribute(flash_kernel, cudaFuncAttributeMaxDynamicSharedMemorySize, fsmem);

    gemm_kernel<1><<<dim3(NQKV_ / 128, M_ / 128), 256, gsmem>>>(nullptr);
    flash_kernel<<<dim3(T_ / 128, BH_), 256, fsmem>>>();
    gemm_kernel<2><<<dim3(C_ / 128, M_ / 128), 256, gsmem>>>(out);
}